// round 4
// baseline (speedup 1.0000x reference)
#include <cuda_runtime.h>
#include <cuda_bf16.h>

#define TPB    128         // 64 rows/block; even lane = pred, odd lane = gt
#define ROWS_B 64
#define ROWF   60
#define NSTEP  10

__device__ float        g_partials[8192];
__device__ unsigned int g_count = 0;

// ---------------------------------------------------------------------------
// fast atan2: max abs err ~1e-5 rad (rotation terms carry ~1e-5 of loss mass)
// ---------------------------------------------------------------------------
__device__ __forceinline__ float atan_core(float a) {   // a in [0,1]
    float s  = a * a;
    float r  = fmaf(0.024840285f, s, -0.11643287f);
    r = fmaf(r, s, 0.19354346f);
    r = fmaf(r, s, -0.33262348f);
    r = fmaf(r, s, 0.99997726f);
    return a * r;
}

__device__ __forceinline__ float fast_atan2f(float y, float x) {
    float ax = fabsf(x), ay = fabsf(y);
    float mx = fmaxf(ax, ay);
    float mn = fminf(ax, ay);
    float r  = atan_core(__fdividef(mn, mx));
    if (ay > ax)   r = 1.57079632679489662f - r;
    if (x < 0.0f)  r = 3.14159265358979323f - r;
    return copysignf(r, y);
}

// x >= 0 guaranteed
__device__ __forceinline__ float fast_atan2_posx(float y, float x) {
    float ay = fabsf(y);
    float mx = fmaxf(x, ay);
    float mn = fminf(x, ay);
    float r  = atan_core(__fdividef(mn, mx));
    if (ay > x) r = 1.57079632679489662f - r;
    return copysignf(r, y);
}

// only the 7 rotation-matrix entries matrix_to_euler ever reads
struct M7 { float m0, m3, m4, m5, m6, m7, m8; };

__device__ __forceinline__ M7 euler_to_mat7(float x, float y, float z) {
    float cx, sx, cy, sy, cz, sz;
    __sincosf(x, &sx, &cx);
    __sincosf(y, &sy, &cy);
    __sincosf(z, &sz, &cz);
    M7 R;
    R.m0 = cz * cy;
    R.m3 = sz * cy;
    R.m4 = sz * sy * sx + cz * cx;
    R.m5 = sz * sy * cx - cz * sx;
    R.m6 = -sy;
    R.m7 = cy * sx;
    R.m8 = cy * cx;
    return R;
}

// 3-atan2 euler extraction of M = R1 .* p (select inputs, no extra atan2)
__device__ __forceinline__ void rot_euler(const M7& R1, const M7& p,
                                          float& e0, float& e1, float& e2) {
    float M00 = R1.m0 * p.m0;
    float M10 = R1.m3 * p.m3;
    float M20 = R1.m6 * p.m6;
    float M21 = R1.m7 * p.m7;
    float M22 = R1.m8 * p.m8;
    float M11 = R1.m4 * p.m4;
    float M12 = R1.m5 * p.m5;
    float sy  = sqrtf(fmaf(M00, M00, M10 * M10));
    bool sing = sy < 1e-6f;
    float y0 = sing ? -M12 : M21;
    float x0 = sing ?  M11 : M22;
    float y2 = sing ?  0.0f : M10;
    float x2 = sing ?  1.0f : M00;
    e0 = fast_atan2f(y0, x0);
    e1 = fast_atan2_posx(-M20, sy);
    e2 = fast_atan2f(y2, x2);
}

__device__ __forceinline__ void cpmul(M7& p, const M7& R) {
    p.m0 *= R.m0; p.m3 *= R.m3; p.m4 *= R.m4; p.m5 *= R.m5;
    p.m6 *= R.m6; p.m7 *= R.m7; p.m8 *= R.m8;
}

__global__ void __launch_bounds__(TPB, 8)
cycle_loss_kernel(const float* __restrict__ pred, const float* __restrict__ gt,
                  float* __restrict__ out, double scale)
{
    const int tid = threadIdx.x;
    const int gid = blockIdx.x * TPB + tid;
    const int row = gid >> 1;
    const float* base = (gid & 1) ? gt : pred;
    const float4* r4  = (const float4*)(base + row * ROWF);   // 15 float4 per row

    float acc = 0.0f;

    // ---- peel steps 0,1 ----
    float4 f0 = r4[0], f1 = r4[1], f2 = r4[2];

    // translation state
    float v0 = f0.x, v1 = f0.y, v2 = f0.z;          // t of step 0
    {
        float d0 = v0 - __shfl_xor_sync(0xffffffffu, v0, 1);
        float d1 = v1 - __shfl_xor_sync(0xffffffffu, v1, 1);
        float d2 = v2 - __shfl_xor_sync(0xffffffffu, v2, 1);
        acc += d0 * d0 + d1 * d1 + d2 * d2;
    }
    // step 1: v = 2v + 0
    v0 = 2.0f * v0; v1 = 2.0f * v1; v2 = 2.0f * v2;
    {
        float d0 = v0 - __shfl_xor_sync(0xffffffffu, v0, 1);
        float d1 = v1 - __shfl_xor_sync(0xffffffffu, v1, 1);
        float d2 = v2 - __shfl_xor_sync(0xffffffffu, v2, 1);
        acc += d0 * d0 + d1 * d1 + d2 * d2;
    }
    float c0 = f1.z, c1 = f1.w, c2 = f2.x;          // c = t of step 1

    // rotation state
    M7 R0 = euler_to_mat7(f0.w, f1.x, f1.y);        // r of step 0
    M7 R1 = euler_to_mat7(f2.y, f2.z, f2.w);        // r of step 1
    M7 p;
    {   // rot i=0: M = R1 .* ones
        M7 ones = {1.f, 1.f, 1.f, 1.f, 1.f, 1.f, 1.f};
        float e0, e1, e2;
        rot_euler(R1, ones, e0, e1, e2);
        float d0 = e0 - __shfl_xor_sync(0xffffffffu, e0, 1);
        float d1 = e1 - __shfl_xor_sync(0xffffffffu, e1, 1);
        float d2 = e2 - __shfl_xor_sync(0xffffffffu, e2, 1);
        acc += d0 * d0 + d1 * d1 + d2 * d2;
        p = R0;
    }
    {   // rot i=1: M = R1 .* R0
        float e0, e1, e2;
        rot_euler(R1, p, e0, e1, e2);
        float d0 = e0 - __shfl_xor_sync(0xffffffffu, e0, 1);
        float d1 = e1 - __shfl_xor_sync(0xffffffffu, e1, 1);
        float d2 = e2 - __shfl_xor_sync(0xffffffffu, e2, 1);
        acc += d0 * d0 + d1 * d1 + d2 * d2;
        cpmul(p, R1);
    }

    // ---- steps 2k, 2k+1 for k = 1..4, exactly 3 float4 loads per k ----
    #pragma unroll
    for (int k = 1; k < 5; k++) {
        f0 = r4[3 * k]; f1 = r4[3 * k + 1]; f2 = r4[3 * k + 2];
        // layout: f0 = [t0 t1 t2 r0]  f1 = [r1 r2 t0' t1']  f2 = [t2' r0' r1' r2']

        // translation step i=2k
        v0 = fmaf(2.0f, v0, c0);
        v1 = fmaf(2.0f, v1, c1);
        v2 = fmaf(2.0f, v2, c2);
        {
            float d0 = v0 - __shfl_xor_sync(0xffffffffu, v0, 1);
            float d1 = v1 - __shfl_xor_sync(0xffffffffu, v1, 1);
            float d2 = v2 - __shfl_xor_sync(0xffffffffu, v2, 1);
            acc += d0 * d0 + d1 * d1 + d2 * d2;
        }
        c0 += f0.x; c1 += f0.y; c2 += f0.z;
        // translation step i=2k+1
        v0 = fmaf(2.0f, v0, c0);
        v1 = fmaf(2.0f, v1, c1);
        v2 = fmaf(2.0f, v2, c2);
        {
            float d0 = v0 - __shfl_xor_sync(0xffffffffu, v0, 1);
            float d1 = v1 - __shfl_xor_sync(0xffffffffu, v1, 1);
            float d2 = v2 - __shfl_xor_sync(0xffffffffu, v2, 1);
            acc += d0 * d0 + d1 * d1 + d2 * d2;
        }
        c0 += f1.z; c1 += f1.w; c2 += f2.x;

        // rotation step i=2k  (p == P_2k here)
        {
            float e0, e1, e2;
            rot_euler(R1, p, e0, e1, e2);
            float d0 = e0 - __shfl_xor_sync(0xffffffffu, e0, 1);
            float d1 = e1 - __shfl_xor_sync(0xffffffffu, e1, 1);
            float d2 = e2 - __shfl_xor_sync(0xffffffffu, e2, 1);
            acc += d0 * d0 + d1 * d1 + d2 * d2;
            M7 R = euler_to_mat7(f0.w, f1.x, f1.y);     // R_{2k}
            cpmul(p, R);
        }
        // rotation step i=2k+1
        {
            float e0, e1, e2;
            rot_euler(R1, p, e0, e1, e2);
            float d0 = e0 - __shfl_xor_sync(0xffffffffu, e0, 1);
            float d1 = e1 - __shfl_xor_sync(0xffffffffu, e1, 1);
            float d2 = e2 - __shfl_xor_sync(0xffffffffu, e2, 1);
            acc += d0 * d0 + d1 * d1 + d2 * d2;
            if (k < 4) {                                 // R_9 never used
                M7 R = euler_to_mat7(f2.y, f2.z, f2.w);  // R_{2k+1}
                cpmul(p, R);
            }
        }
    }

    // ---------------- block reduction ----------------
    #pragma unroll
    for (int o = 16; o > 0; o >>= 1)
        acc += __shfl_down_sync(0xffffffffu, acc, o);

    __shared__ float wsum[TPB / 32];
    if ((tid & 31) == 0) wsum[tid >> 5] = acc;
    __syncthreads();

    __shared__ bool is_last;
    if (tid == 0) {
        float sblk = 0.0f;
        #pragma unroll
        for (int w = 0; w < TPB / 32; w++) sblk += wsum[w];
        g_partials[blockIdx.x] = sblk;
        __threadfence();
        unsigned int c = atomicAdd(&g_count, 1u);
        is_last = (c == gridDim.x - 1);
    }
    __syncthreads();

    // ---------------- last block: deterministic final reduce ----------------
    if (is_last) {
        double sd = 0.0;
        for (int i = tid; i < (int)gridDim.x; i += TPB)
            sd += (double)g_partials[i];
        #pragma unroll
        for (int o = 16; o > 0; o >>= 1)
            sd += __shfl_down_sync(0xffffffffu, sd, o);
        __shared__ double dsum[TPB / 32];
        if ((tid & 31) == 0) dsum[tid >> 5] = sd;
        __syncthreads();
        if (tid == 0) {
            double t = 0.0;
            #pragma unroll
            for (int w = 0; w < TPB / 32; w++) t += dsum[w];
            out[0] = (float)(t * scale);
            g_count = 0;            // reset for next graph replay
        }
    }
}

extern "C" void kernel_launch(void* const* d_in, const int* in_sizes, int n_in,
                              void* d_out, int out_size)
{
    const float* pred = (const float*)d_in[0];
    const float* gt   = (const float*)d_in[1];
    int batch   = in_sizes[0] / ROWF;       // 262144
    int nblocks = batch / ROWS_B;           // 4096

    // loss = sum / (60 * B * B); extra 0.5: both lanes of a pair accumulate
    // the same squared difference.
    double scale = 0.5 / (60.0 * (double)batch * (double)batch);
    cycle_loss_kernel<<<nblocks, TPB>>>(pred, gt, (float*)d_out, scale);
}

// round 5
// speedup vs baseline: 1.1533x; 1.1533x over previous
#include <cuda_runtime.h>
#include <cuda_bf16.h>

#define TPB    128         // 64 rows/block; even lane = pred, odd lane = gt
#define ROWS_B 64
#define ROWF   60
#define STR    33          // smem row stride (odd -> conflict-free)
#define GTOFF  (ROWS_B * STR + 16)   // +16: lane pairs hit disjoint bank halves
#define NSTEP  10

__device__ float        g_partials[8192];
__device__ unsigned int g_count = 0;

// ---------------------------------------------------------------------------
// fast atan2: max abs err ~1e-5 rad (rotation terms carry ~1e-5 of loss mass)
// ---------------------------------------------------------------------------
__device__ __forceinline__ float atan_core(float a) {   // a in [0,1]
    float s  = a * a;
    float r  = fmaf(0.024840285f, s, -0.11643287f);
    r = fmaf(r, s, 0.19354346f);
    r = fmaf(r, s, -0.33262348f);
    r = fmaf(r, s, 0.99997726f);
    return a * r;
}

__device__ __forceinline__ float fast_atan2f(float y, float x) {
    float ax = fabsf(x), ay = fabsf(y);
    float mx = fmaxf(ax, ay);
    float mn = fminf(ax, ay);
    float r  = atan_core(__fdividef(mn, mx));
    if (ay > ax)   r = 1.57079632679489662f - r;
    if (x < 0.0f)  r = 3.14159265358979323f - r;
    return copysignf(r, y);
}

// x >= 0 guaranteed
__device__ __forceinline__ float fast_atan2_posx(float y, float x) {
    float ay = fabsf(y);
    float mx = fmaxf(x, ay);
    float mn = fminf(x, ay);
    float r  = atan_core(__fdividef(mn, mx));
    if (ay > x) r = 1.57079632679489662f - r;
    return copysignf(r, y);
}

// only the 7 rotation-matrix entries matrix_to_euler ever reads
struct M7 { float m0, m3, m4, m5, m6, m7, m8; };

__device__ __forceinline__ M7 euler_to_mat7(float x, float y, float z) {
    float cx, sx, cy, sy, cz, sz;
    __sincosf(x, &sx, &cx);
    __sincosf(y, &sy, &cy);
    __sincosf(z, &sz, &cz);
    M7 R;
    R.m0 = cz * cy;
    R.m3 = sz * cy;
    R.m4 = sz * sy * sx + cz * cx;
    R.m5 = sz * sy * cx - cz * sx;
    R.m6 = -sy;
    R.m7 = cy * sx;
    R.m8 = cy * cx;
    return R;
}

// 3-atan2 euler extraction of M = R1 .* p (select inputs, no extra atan2)
__device__ __forceinline__ void rot_euler(const M7& R1, const M7& p,
                                          float& e0, float& e1, float& e2) {
    float M00 = R1.m0 * p.m0;
    float M10 = R1.m3 * p.m3;
    float M20 = R1.m6 * p.m6;
    float M21 = R1.m7 * p.m7;
    float M22 = R1.m8 * p.m8;
    float M11 = R1.m4 * p.m4;
    float M12 = R1.m5 * p.m5;
    float sy  = sqrtf(fmaf(M00, M00, M10 * M10));
    bool sing = sy < 1e-6f;
    float y0 = sing ? -M12 : M21;
    float x0 = sing ?  M11 : M22;
    float y2 = sing ?  0.0f : M10;
    float x2 = sing ?  1.0f : M00;
    e0 = fast_atan2f(y0, x0);
    e1 = fast_atan2_posx(-M20, sy);
    e2 = fast_atan2f(y2, x2);
}

__device__ __forceinline__ void cpmul(M7& p, const M7& R) {
    p.m0 *= R.m0; p.m3 *= R.m3; p.m4 *= R.m4; p.m5 *= R.m5;
    p.m6 *= R.m6; p.m7 *= R.m7; p.m8 *= R.m8;
}

__global__ void __launch_bounds__(TPB, 8)
cycle_loss_kernel(const float* __restrict__ pred, const float* __restrict__ gt,
                  float* __restrict__ out, double scale)
{
    __shared__ float sbuf[2 * ROWS_B * STR + 16];
    const int tid = threadIdx.x;
    const long gbase = (long)blockIdx.x * ROWS_B * ROWF;
    const float4* p4 = (const float4*)(pred + gbase);
    const float4* g4 = (const float4*)(gt   + gbase);

    // ---- phase A stage: floats [0,32) of each row (8 float4) ----
    #pragma unroll
    for (int j = tid; j < ROWS_B * 8; j += TPB) {
        int r = j >> 3, c = j & 7;
        float4 v = p4[r * 15 + c];
        float* d = &sbuf[r * STR + 4 * c];
        d[0] = v.x; d[1] = v.y; d[2] = v.z; d[3] = v.w;
        float4 w = g4[r * 15 + c];
        float* e = &sbuf[GTOFF + r * STR + 4 * c];
        e[0] = w.x; e[1] = w.y; e[2] = w.z; e[3] = w.w;
    }
    __syncthreads();

    const float* P = &sbuf[(tid & 1) * GTOFF + (tid >> 1) * STR];

    float acc = 0.0f;
    float v0, v1, v2, c0, c1, c2;
    M7 R1, p;

    // ---- phase A compute: steps 0-4 ----
    {
        // step 0
        v0 = P[0]; v1 = P[1]; v2 = P[2];
        {
            float d0 = v0 - __shfl_xor_sync(0xffffffffu, v0, 1);
            float d1 = v1 - __shfl_xor_sync(0xffffffffu, v1, 1);
            float d2 = v2 - __shfl_xor_sync(0xffffffffu, v2, 1);
            acc += d0 * d0 + d1 * d1 + d2 * d2;
        }
        M7 R0 = euler_to_mat7(P[3], P[4], P[5]);
        R1 = euler_to_mat7(P[9], P[10], P[11]);
        {
            M7 ones = {1.f, 1.f, 1.f, 1.f, 1.f, 1.f, 1.f};
            float e0, e1, e2;
            rot_euler(R1, ones, e0, e1, e2);
            float d0 = e0 - __shfl_xor_sync(0xffffffffu, e0, 1);
            float d1 = e1 - __shfl_xor_sync(0xffffffffu, e1, 1);
            float d2 = e2 - __shfl_xor_sync(0xffffffffu, e2, 1);
            acc += d0 * d0 + d1 * d1 + d2 * d2;
        }
        p = R0;

        // step 1
        v0 = 2.0f * v0; v1 = 2.0f * v1; v2 = 2.0f * v2;
        {
            float d0 = v0 - __shfl_xor_sync(0xffffffffu, v0, 1);
            float d1 = v1 - __shfl_xor_sync(0xffffffffu, v1, 1);
            float d2 = v2 - __shfl_xor_sync(0xffffffffu, v2, 1);
            acc += d0 * d0 + d1 * d1 + d2 * d2;
        }
        c0 = P[6]; c1 = P[7]; c2 = P[8];
        {
            float e0, e1, e2;
            rot_euler(R1, p, e0, e1, e2);
            float d0 = e0 - __shfl_xor_sync(0xffffffffu, e0, 1);
            float d1 = e1 - __shfl_xor_sync(0xffffffffu, e1, 1);
            float d2 = e2 - __shfl_xor_sync(0xffffffffu, e2, 1);
            acc += d0 * d0 + d1 * d1 + d2 * d2;
        }
        cpmul(p, R1);

        // steps 2-4
        #pragma unroll
        for (int i = 2; i <= 4; i++) {
            const float* S = &P[6 * i];
            v0 = fmaf(2.0f, v0, c0);
            v1 = fmaf(2.0f, v1, c1);
            v2 = fmaf(2.0f, v2, c2);
            {
                float d0 = v0 - __shfl_xor_sync(0xffffffffu, v0, 1);
                float d1 = v1 - __shfl_xor_sync(0xffffffffu, v1, 1);
                float d2 = v2 - __shfl_xor_sync(0xffffffffu, v2, 1);
                acc += d0 * d0 + d1 * d1 + d2 * d2;
            }
            c0 += S[0]; c1 += S[1]; c2 += S[2];
            {
                float e0, e1, e2;
                rot_euler(R1, p, e0, e1, e2);
                float d0 = e0 - __shfl_xor_sync(0xffffffffu, e0, 1);
                float d1 = e1 - __shfl_xor_sync(0xffffffffu, e1, 1);
                float d2 = e2 - __shfl_xor_sync(0xffffffffu, e2, 1);
                acc += d0 * d0 + d1 * d1 + d2 * d2;
            }
            M7 R = euler_to_mat7(S[3], S[4], S[5]);
            cpmul(p, R);
        }
    }

    // carry floats 30,31 (t0,t1 of step 5) across the restage
    float s30 = P[30], s31 = P[31];
    __syncthreads();

    // ---- phase B stage: floats [32,60) of each row (7 float4) ----
    #pragma unroll
    for (int j = tid; j < ROWS_B * 8; j += TPB) {
        int r = j >> 3, c = j & 7;
        if (c < 7) {
            float4 v = p4[r * 15 + 8 + c];
            float* d = &sbuf[r * STR + 4 * c];
            d[0] = v.x; d[1] = v.y; d[2] = v.z; d[3] = v.w;
            float4 w = g4[r * 15 + 8 + c];
            float* e = &sbuf[GTOFF + r * STR + 4 * c];
            e[0] = w.x; e[1] = w.y; e[2] = w.z; e[3] = w.w;
        }
    }
    __syncthreads();

    // ---- phase B compute: steps 5-9 (buffer holds floats 32..59 at 0..27) ----
    {
        // step 5: t = (s30, s31, P[0]); r = (P[1], P[2], P[3])
        v0 = fmaf(2.0f, v0, c0);
        v1 = fmaf(2.0f, v1, c1);
        v2 = fmaf(2.0f, v2, c2);
        {
            float d0 = v0 - __shfl_xor_sync(0xffffffffu, v0, 1);
            float d1 = v1 - __shfl_xor_sync(0xffffffffu, v1, 1);
            float d2 = v2 - __shfl_xor_sync(0xffffffffu, v2, 1);
            acc += d0 * d0 + d1 * d1 + d2 * d2;
        }
        c0 += s30; c1 += s31; c2 += P[0];
        {
            float e0, e1, e2;
            rot_euler(R1, p, e0, e1, e2);
            float d0 = e0 - __shfl_xor_sync(0xffffffffu, e0, 1);
            float d1 = e1 - __shfl_xor_sync(0xffffffffu, e1, 1);
            float d2 = e2 - __shfl_xor_sync(0xffffffffu, e2, 1);
            acc += d0 * d0 + d1 * d1 + d2 * d2;
        }
        {
            M7 R = euler_to_mat7(P[1], P[2], P[3]);
            cpmul(p, R);
        }

        // steps 6-9: float f -> P[f - 32]
        #pragma unroll
        for (int i = 6; i <= 9; i++) {
            const float* S = &P[6 * i - 32];
            v0 = fmaf(2.0f, v0, c0);
            v1 = fmaf(2.0f, v1, c1);
            v2 = fmaf(2.0f, v2, c2);
            {
                float d0 = v0 - __shfl_xor_sync(0xffffffffu, v0, 1);
                float d1 = v1 - __shfl_xor_sync(0xffffffffu, v1, 1);
                float d2 = v2 - __shfl_xor_sync(0xffffffffu, v2, 1);
                acc += d0 * d0 + d1 * d1 + d2 * d2;
            }
            {
                float e0, e1, e2;
                rot_euler(R1, p, e0, e1, e2);
                float d0 = e0 - __shfl_xor_sync(0xffffffffu, e0, 1);
                float d1 = e1 - __shfl_xor_sync(0xffffffffu, e1, 1);
                float d2 = e2 - __shfl_xor_sync(0xffffffffu, e2, 1);
                acc += d0 * d0 + d1 * d1 + d2 * d2;
            }
            if (i < 9) {
                c0 += S[0]; c1 += S[1]; c2 += S[2];
                M7 R = euler_to_mat7(S[3], S[4], S[5]);
                cpmul(p, R);
            }
        }
    }

    // ---------------- block reduction ----------------
    #pragma unroll
    for (int o = 16; o > 0; o >>= 1)
        acc += __shfl_down_sync(0xffffffffu, acc, o);

    __shared__ float wsum[TPB / 32];
    if ((tid & 31) == 0) wsum[tid >> 5] = acc;
    __syncthreads();

    __shared__ bool is_last;
    if (tid == 0) {
        float sblk = 0.0f;
        #pragma unroll
        for (int w = 0; w < TPB / 32; w++) sblk += wsum[w];
        g_partials[blockIdx.x] = sblk;
        __threadfence();
        unsigned int c = atomicAdd(&g_count, 1u);
        is_last = (c == gridDim.x - 1);
    }
    __syncthreads();

    // ---------------- last block: deterministic final reduce ----------------
    if (is_last) {
        double sd = 0.0;
        for (int i = tid; i < (int)gridDim.x; i += TPB)
            sd += (double)g_partials[i];
        #pragma unroll
        for (int o = 16; o > 0; o >>= 1)
            sd += __shfl_down_sync(0xffffffffu, sd, o);
        __shared__ double dsum[TPB / 32];
        if ((tid & 31) == 0) dsum[tid >> 5] = sd;
        __syncthreads();
        if (tid == 0) {
            double t = 0.0;
            #pragma unroll
            for (int w = 0; w < TPB / 32; w++) t += dsum[w];
            out[0] = (float)(t * scale);
            g_count = 0;            // reset for next graph replay
        }
    }
}

extern "C" void kernel_launch(void* const* d_in, const int* in_sizes, int n_in,
                              void* d_out, int out_size)
{
    const float* pred = (const float*)d_in[0];
    const float* gt   = (const float*)d_in[1];
    int batch   = in_sizes[0] / ROWF;       // 262144
    int nblocks = batch / ROWS_B;           // 4096

    // loss = sum / (60 * B * B); extra 0.5: both lanes of a pair accumulate
    // the same squared difference.
    double scale = 0.5 / (60.0 * (double)batch * (double)batch);
    cycle_loss_kernel<<<nblocks, TPB>>>(pred, gt, (float*)d_out, scale);
}